// round 15
// baseline (speedup 1.0000x reference)
#include <cuda_runtime.h>
#include <cuda_bf16.h>
#include <cstdint>

// Problem dims
#define Ldim 2
#define Bdim 8
#define Tdim 256
#define Ndim 512
#define Kdim 16
#define Mdim 10000
#define Hdim 256
#define Rdim 500

// Scratch (device globals -- no allocation allowed)
__device__ float g_u0[Bdim * Ndim * Hdim];       // 4 MB
__device__ float g_q[Bdim * Tdim * Hdim];        // 2 MB
__device__ float g_k[Bdim * Ndim * Hdim];        // 4 MB
__device__ float g_ewd[Bdim * Tdim * Hdim];      // 2 MB : exp(-(h@wd.T+bd))
__device__ float g_ug[Bdim * Tdim * Hdim];       // 2 MB
__device__ float g_pasi[Bdim * Tdim * Ndim];     // 4 MB
__device__ float g_a[Bdim];

__device__ __forceinline__ float warp_sum(float v) {
    #pragma unroll
    for (int o = 16; o > 0; o >>= 1) v += __shfl_xor_sync(0xffffffffu, v, o);
    return v;
}
__device__ __forceinline__ float warp_max(float v) {
    #pragma unroll
    for (int o = 16; o > 0; o >>= 1) v = fmaxf(v, __shfl_xor_sync(0xffffffffu, v, o));
    return v;
}

#define WT_PITCH 258   // even pitch: float2 reads 8B-aligned & conflict-free

#define PREP_XS_FLOATS   (16 * 512)
#define PREP_WT_FLOATS   (32 * WT_PITCH)
#define PREP_SMEM_BYTES  ((PREP_XS_FLOATS + PREP_WT_FLOATS) * 4 + 512 * 4)

// Cooperatively load a 32(j) x 256(o) tile of a row-major weight W[o][ld]
// into wt[jj*WT_PITCH + o], fully coalesced from global.
__device__ __forceinline__ void load_wtile(
    float* wt, const float* __restrict__ W, int ld, int j0, int tid)
{
    #pragma unroll
    for (int i = 0; i < 8; i++) {
        int lin = i * 256 + tid;          // indexes (o, j4)
        int o   = lin >> 3;
        int j4  = lin & 7;
        float4 w = *(const float4*)(W + (size_t)o * ld + j0 + j4 * 4);
        wt[(j4 * 4 + 0) * WT_PITCH + o] = w.x;
        wt[(j4 * 4 + 1) * WT_PITCH + o] = w.y;
        wt[(j4 * 4 + 2) * WT_PITCH + o] = w.z;
        wt[(j4 * 4 + 3) * WT_PITCH + o] = w.w;
    }
}

// ---------------------------------------------------------------------------
// prep_kernel: fused u0 + qdg + k + aerfa with SMEM-tiled weights and
// TMxTN register tiling. u0 path now 512 blocks x 8 rows (was 256 x 16) to
// double the concurrent DRAM gather streams (prep appears gather-bound:
// ~70MB of SE rows at only 538 GB/s).
//   blocks [0,512)     : u0 rows (8 each; halves of 128 thr take 4 rows)
//   blocks [512,768)   : qdg rows (8 each; halves take 4 rows, 3 matrices)
//   blocks [768,1024)  : k rows (16 each)
//   block  1024        : aerfa
// ---------------------------------------------------------------------------
__global__ __launch_bounds__(256) void prep_kernel(
    const float* __restrict__ SE,          // (B,M,H)
    const int*   __restrict__ heads,       // (B,N,K)
    const int*   __restrict__ tails,       // (B,N,K)
    const float* __restrict__ squeeze_w,   // (H,2H)
    const float* __restrict__ squeeze_b,   // (H)
    const int*   __restrict__ tri_mask,    // (B,N)
    const float* __restrict__ hlast,       // (B*T, H)
    const float* __restrict__ wq, const float* __restrict__ bq,
    const float* __restrict__ wd, const float* __restrict__ bd,
    const float* __restrict__ wg, const float* __restrict__ bg,
    const float* __restrict__ rel_table,   // (R,H)
    const int*   __restrict__ ridx_g,      // (B,N)
    const float* __restrict__ wk, const float* __restrict__ bk,
    const float* __restrict__ aw, const float* __restrict__ abias)
{
    extern __shared__ float dyn_smem[];
    float* xs_f   = dyn_smem;                          // up to 16*512 floats
    float* wt     = dyn_smem + PREP_XS_FLOATS;         // 32*WT_PITCH floats
    int*   smem_i = (int*)(dyn_smem + PREP_XS_FLOATS + PREP_WT_FLOATS);

    const int tid  = threadIdx.x;
    const int blk  = blockIdx.x;
    const int half = tid >> 7;             // 0 or 1 (row-half)
    const int o0   = (tid & 127) * 2;      // this thread's 2 output cols

    if (blk < 512) {
        // ---------------- u0 path: 8 (b,n) rows, K=512 ----------------
        int (*sidx)[32] = (int(*)[32])smem_i;
        const int row0 = blk * 8;
        const int b    = row0 / Ndim;

        for (int i = tid; i < 8 * 32; i += 256) {
            int r = i >> 5, j = i & 31;
            int gr = row0 + r;
            sidx[r][j] = (j < 16) ? heads[gr * Kdim + j] : tails[gr * Kdim + (j - 16)];
        }
        __syncthreads();

        const float* SEb = SE + (size_t)b * Mdim * Hdim;
        for (int r = 0; r < 8; r++) {
            float he = 0.f, te = 0.f;
            #pragma unroll
            for (int k = 0; k < 16; k++) {
                he += SEb[(size_t)sidx[r][k] * Hdim + tid];
                te += SEb[(size_t)sidx[r][16 + k] * Hdim + tid];
            }
            xs_f[r * 512 + tid]       = he;
            xs_f[r * 512 + 256 + tid] = te;
        }
        __syncthreads();

        const int rbase = half * 4;
        float acc[4][2];
        #pragma unroll
        for (int r = 0; r < 4; r++) { acc[r][0] = 0.f; acc[r][1] = 0.f; }

        for (int j0 = 0; j0 < 512; j0 += 32) {
            load_wtile(wt, squeeze_w, 512, j0, tid);
            __syncthreads();
            #pragma unroll
            for (int g = 0; g < 8; g++) {
                float2 wv0 = *(const float2*)&wt[(g*4+0) * WT_PITCH + o0];
                float2 wv1 = *(const float2*)&wt[(g*4+1) * WT_PITCH + o0];
                float2 wv2 = *(const float2*)&wt[(g*4+2) * WT_PITCH + o0];
                float2 wv3 = *(const float2*)&wt[(g*4+3) * WT_PITCH + o0];
                #pragma unroll
                for (int r = 0; r < 4; r++) {
                    float4 xv = *(const float4*)&xs_f[(rbase + r) * 512 + j0 + g*4];
                    acc[r][0] = fmaf(xv.x, wv0.x, acc[r][0]);
                    acc[r][1] = fmaf(xv.x, wv0.y, acc[r][1]);
                    acc[r][0] = fmaf(xv.y, wv1.x, acc[r][0]);
                    acc[r][1] = fmaf(xv.y, wv1.y, acc[r][1]);
                    acc[r][0] = fmaf(xv.z, wv2.x, acc[r][0]);
                    acc[r][1] = fmaf(xv.z, wv2.y, acc[r][1]);
                    acc[r][0] = fmaf(xv.w, wv3.x, acc[r][0]);
                    acc[r][1] = fmaf(xv.w, wv3.y, acc[r][1]);
                }
            }
            __syncthreads();
        }
        float b0 = squeeze_b[o0], b1 = squeeze_b[o0 + 1];
        for (int r = 0; r < 4; r++) {
            int gr = row0 + rbase + r;
            int ok = (tri_mask[gr] == 1);
            float2 v = make_float2(ok ? acc[r][0] + b0 : 0.f,
                                   ok ? acc[r][1] + b1 : 0.f);
            *(float2*)&g_u0[(size_t)gr * Hdim + o0] = v;
        }
    } else if (blk < 768) {
        // ---------------- qdg path: 8 rows, 3 weights, K=256 ----------------
        const int row0 = (blk - 512) * 8;
        for (int r = 0; r < 8; r++)
            xs_f[r * 256 + tid] = hlast[(size_t)(row0 + r) * Hdim + tid];
        __syncthreads();

        const int rbase = half * 4;
        float accq[4][2], accd[4][2], accg[4][2];
        #pragma unroll
        for (int r = 0; r < 4; r++) {
            accq[r][0]=accq[r][1]=accd[r][0]=accd[r][1]=accg[r][0]=accg[r][1]=0.f;
        }

        const float* Ws[3] = {wq, wd, wg};
        #pragma unroll
        for (int wsel = 0; wsel < 3; wsel++) {
            const float* W = Ws[wsel];
            float acc[4][2];
            #pragma unroll
            for (int r = 0; r < 4; r++) { acc[r][0] = 0.f; acc[r][1] = 0.f; }
            for (int j0 = 0; j0 < 256; j0 += 32) {
                load_wtile(wt, W, 256, j0, tid);
                __syncthreads();
                #pragma unroll
                for (int g = 0; g < 8; g++) {
                    float2 wv0 = *(const float2*)&wt[(g*4+0) * WT_PITCH + o0];
                    float2 wv1 = *(const float2*)&wt[(g*4+1) * WT_PITCH + o0];
                    float2 wv2 = *(const float2*)&wt[(g*4+2) * WT_PITCH + o0];
                    float2 wv3 = *(const float2*)&wt[(g*4+3) * WT_PITCH + o0];
                    #pragma unroll
                    for (int r = 0; r < 4; r++) {
                        float4 xv = *(const float4*)&xs_f[(rbase + r) * 256 + j0 + g*4];
                        acc[r][0] = fmaf(xv.x, wv0.x, acc[r][0]);
                        acc[r][1] = fmaf(xv.x, wv0.y, acc[r][1]);
                        acc[r][0] = fmaf(xv.y, wv1.x, acc[r][0]);
                        acc[r][1] = fmaf(xv.y, wv1.y, acc[r][1]);
                        acc[r][0] = fmaf(xv.z, wv2.x, acc[r][0]);
                        acc[r][1] = fmaf(xv.z, wv2.y, acc[r][1]);
                        acc[r][0] = fmaf(xv.w, wv3.x, acc[r][0]);
                        acc[r][1] = fmaf(xv.w, wv3.y, acc[r][1]);
                    }
                }
                __syncthreads();
            }
            #pragma unroll
            for (int r = 0; r < 4; r++) {
                if (wsel == 0)      { accq[r][0] = acc[r][0]; accq[r][1] = acc[r][1]; }
                else if (wsel == 1) { accd[r][0] = acc[r][0]; accd[r][1] = acc[r][1]; }
                else                { accg[r][0] = acc[r][0]; accg[r][1] = acc[r][1]; }
            }
        }
        float bq0 = bq[o0], bq1 = bq[o0+1];
        float bd0 = bd[o0], bd1 = bd[o0+1];
        float bg0 = bg[o0], bg1 = bg[o0+1];
        for (int r = 0; r < 4; r++) {
            size_t o = (size_t)(row0 + rbase + r) * Hdim + o0;
            *(float2*)&g_q[o]   = make_float2((accq[r][0] + bq0) * 0.0625f,
                                              (accq[r][1] + bq1) * 0.0625f);
            *(float2*)&g_ewd[o] = make_float2(__expf(-(accd[r][0] + bd0)),
                                              __expf(-(accd[r][1] + bd1)));
            *(float2*)&g_ug[o]  = make_float2(accg[r][0] + bg0,
                                              accg[r][1] + bg1);
        }
    } else if (blk < 1024) {
        // ---------------- k path: 16 rows, K=256 ----------------
        int* ridx = smem_i;
        const int row0 = (blk - 768) * 16;
        if (tid < 16) ridx[tid] = ridx_g[row0 + tid];
        __syncthreads();
        for (int i = tid; i < 16 * 256; i += 256) {
            int r = i >> 8, j = i & 255;
            xs_f[r * 256 + j] = rel_table[(size_t)ridx[r] * Hdim + j];
        }
        __syncthreads();

        const int rbase = half * 8;
        float acc[8][2];
        #pragma unroll
        for (int r = 0; r < 8; r++) { acc[r][0] = 0.f; acc[r][1] = 0.f; }

        for (int j0 = 0; j0 < 256; j0 += 32) {
            load_wtile(wt, wk, 256, j0, tid);
            __syncthreads();
            #pragma unroll
            for (int g = 0; g < 8; g++) {
                float2 wv0 = *(const float2*)&wt[(g*4+0) * WT_PITCH + o0];
                float2 wv1 = *(const float2*)&wt[(g*4+1) * WT_PITCH + o0];
                float2 wv2 = *(const float2*)&wt[(g*4+2) * WT_PITCH + o0];
                float2 wv3 = *(const float2*)&wt[(g*4+3) * WT_PITCH + o0];
                #pragma unroll
                for (int r = 0; r < 8; r++) {
                    float4 xv = *(const float4*)&xs_f[(rbase + r) * 256 + j0 + g*4];
                    acc[r][0] = fmaf(xv.x, wv0.x, acc[r][0]);
                    acc[r][1] = fmaf(xv.x, wv0.y, acc[r][1]);
                    acc[r][0] = fmaf(xv.y, wv1.x, acc[r][0]);
                    acc[r][1] = fmaf(xv.y, wv1.y, acc[r][1]);
                    acc[r][0] = fmaf(xv.z, wv2.x, acc[r][0]);
                    acc[r][1] = fmaf(xv.z, wv2.y, acc[r][1]);
                    acc[r][0] = fmaf(xv.w, wv3.x, acc[r][0]);
                    acc[r][1] = fmaf(xv.w, wv3.y, acc[r][1]);
                }
            }
            __syncthreads();
        }
        float bk0 = bk[o0], bk1 = bk[o0 + 1];
        for (int r = 0; r < 8; r++) {
            size_t o = (size_t)(row0 + rbase + r) * Hdim + o0;
            *(float2*)&g_k[o] = make_float2(acc[r][0] + bk0, acc[r][1] + bk1);
        }
    } else {
        // ---------------- aerfa: warp b handles batch b ----------------
        const int b = tid >> 5, lane = tid & 31;
        const float* x = hlast + ((size_t)b * Tdim + (Tdim - 1)) * Hdim;
        float s = 0.f;
        #pragma unroll
        for (int j = lane; j < Hdim; j += 32) s += x[j] * aw[j];
        s = warp_sum(s);
        if (lane == 0) g_a[b] = __fdividef(1.0f, 1.0f + __expf(-(s + abias[0])));
    }
}

// ---------------------------------------------------------------------------
// Kernel 3: scores = q.k^T (masked) then softmax over n -> pasi
// ---------------------------------------------------------------------------
__global__ __launch_bounds__(256) void score_kernel(const int* __restrict__ tri_mask)
{
    __shared__ float qs[8][256];
    __shared__ float sc[8][512];
    const int tid  = threadIdx.x;
    const int row0 = blockIdx.x * 8;       // flattened b*T + t
    const int b    = row0 / Tdim;

    for (int r = 0; r < 8; r++) qs[r][tid] = g_q[(size_t)(row0 + r) * Hdim + tid];
    __syncthreads();

    float a0[8], a1[8];
    #pragma unroll
    for (int r = 0; r < 8; r++) { a0[r] = 0.f; a1[r] = 0.f; }

    const float* kb = g_k + (size_t)b * Ndim * Hdim;
    const float4* K0 = (const float4*)(kb + (size_t)tid * Hdim);
    const float4* K1 = (const float4*)(kb + (size_t)(tid + 256) * Hdim);
    for (int j4 = 0; j4 < 64; j4++) {
        float4 k0 = K0[j4], k1 = K1[j4];
        #pragma unroll
        for (int r = 0; r < 8; r++) {
            float4 q = *(const float4*)&qs[r][j4 * 4];
            a0[r] += q.x * k0.x + q.y * k0.y + q.z * k0.z + q.w * k0.w;
            a1[r] += q.x * k1.x + q.y * k1.y + q.z * k1.z + q.w * k1.w;
        }
    }
    int m0 = tri_mask[b * Ndim + tid];
    int m1 = tri_mask[b * Ndim + tid + 256];
    for (int r = 0; r < 8; r++) {
        sc[r][tid]       = (m0 == 1) ? a0[r] : -1.0e9f;
        sc[r][tid + 256] = (m1 == 1) ? a1[r] : -1.0e9f;
    }
    __syncthreads();

    const int wid = tid >> 5, lane = tid & 31;
    float* row = sc[wid];
    float mx = -3.4e38f;
    #pragma unroll
    for (int i = lane; i < 512; i += 32) mx = fmaxf(mx, row[i]);
    mx = warp_max(mx);
    float sum = 0.f;
    #pragma unroll
    for (int i = lane; i < 512; i += 32) {
        float e = __expf(row[i] - mx);
        row[i] = e;
        sum += e;
    }
    sum = warp_sum(sum);
    float inv = __fdividef(1.0f, sum);
    float* pout = g_pasi + (size_t)(row0 + wid) * Ndim;
    #pragma unroll
    for (int i = lane; i < 512; i += 32) pout[i] = row[i] * inv;
}

// ---------------------------------------------------------------------------
// Kernel 4: sequential scan, npw=2 + DEPTH-3 PREFETCH + float4 h-mapping.
// grid: (N/8, B) = 512 blocks x 128 thr (4 warps). Warp owns 2 n; thread owns
// h = c*128 + 4*lane + {0..3}, c=0,1. 3-stage register pipeline: data for t
// is loaded at t-3 (load-to-use ~3 iterations, fully covers L2 latency that
// the round-14 depth-2 scheme only partially hid). One barrier per t
// (double-buffered SMEM reduction, buffer = t&1).
// ---------------------------------------------------------------------------
__global__ __launch_bounds__(128) void scan_kernel(
    const float* __restrict__ wu_w,        // (1,H)
    const float* __restrict__ wu_b,        // (1)
    float* __restrict__ out)               // (B,T,H)
{
    __shared__ float sacc[2][1024];        // 4 warps x 256 h, x2 buf
    const int b    = blockIdx.y;
    const int wid  = threadIdx.x >> 5;     // 0..3
    const int lane = threadIdx.x & 31;
    const int tid  = threadIdx.x;          // 0..127
    const int n0   = blockIdx.x * 8 + wid * 2;    // this warp's 2 n
    const int h0   = lane * 4;                    // offset within 128-chunk

    float u[2][8], wv[8];
    #pragma unroll
    for (int c = 0; c < 2; c++) {
        float4 ww = *(const float4*)(wu_w + c * 128 + h0);
        wv[c*4+0]=ww.x; wv[c*4+1]=ww.y; wv[c*4+2]=ww.z; wv[c*4+3]=ww.w;
    }
    #pragma unroll
    for (int m = 0; m < 2; m++) {
        const float* ubase = g_u0 + ((size_t)b * Ndim + n0 + m) * Hdim;
        #pragma unroll
        for (int c = 0; c < 2; c++) {
            float4 uu = *(const float4*)(ubase + c * 128 + h0);
            u[m][c*4+0]=uu.x; u[m][c*4+1]=uu.y; u[m][c*4+2]=uu.z; u[m][c*4+3]=uu.w;
        }
    }
    const float wub = wu_b[0];
    const float ab  = g_a[b];
    const float* pas = g_pasi + (size_t)b * Tdim * Ndim + n0;
    const float* edb = g_ewd + (size_t)b * Tdim * Hdim + h0;
    const float* ugb = g_ug  + (size_t)b * Tdim * Hdim + h0;
    float* outb = out + (size_t)b * Tdim * Hdim;

    // 3-stage pipeline: stage[s] holds data for t with (t % 3) == s
    float4 e4[3][2], g4[3][2];   // [stage][chunk]
    float  pv[3][2];             // [stage][m]
    #pragma unroll
    for (int s = 0; s < 3; s++) {
        const float* ed  = edb + (size_t)s * Hdim;
        const float* ugp = ugb + (size_t)s * Hdim;
        #pragma unroll
        for (int c = 0; c < 2; c++) {
            e4[s][c] = *(const float4*)(ed  + c * 128);
            g4[s][c] = *(const float4*)(ugp + c * 128);
        }
        pv[s][0] = pas[(size_t)s * Ndim];
        pv[s][1] = pas[(size_t)s * Ndim + 1];
    }

    #pragma unroll 3
    for (int t = 0; t < Tdim; t++) {
        const int st = t % 3;        // pipeline stage (compile-time w/ unroll 3)
        const int sb = t & 1;        // smem reduction buffer

        // copy stage to locals (frees the stage for the t+3 prefetch below)
        float ew[8]  = {e4[st][0].x, e4[st][0].y, e4[st][0].z, e4[st][0].w,
                        e4[st][1].x, e4[st][1].y, e4[st][1].z, e4[st][1].w};
        float ugv[8] = {g4[st][0].x, g4[st][0].y, g4[st][0].z, g4[st][0].w,
                        g4[st][1].x, g4[st][1].y, g4[st][1].z, g4[st][1].w};
        float p0 = pv[st][0], p1 = pv[st][1];

        // wu[m] = u[m] . wu_w + wu_b  (PRE-update u)
        float s0 = 0.f, s1 = 0.f;
        #pragma unroll
        for (int j = 0; j < 8; j++) {
            s0 = fmaf(u[0][j], wv[j], s0);
            s1 = fmaf(u[1][j], wv[j], s1);
        }
        #pragma unroll
        for (int o = 16; o > 0; o >>= 1) {
            s0 += __shfl_xor_sync(0xffffffffu, s0, o);
            s1 += __shfl_xor_sync(0xffffffffu, s1, o);
        }
        float En0 = __expf(-(s0 + wub));
        float En1 = __expf(-(s1 + wub));

        // prefetch t+3 into stage st (consumed three iterations from now)
        if (t + 3 < Tdim) {
            const float* ed  = edb + (size_t)(t + 3) * Hdim;
            const float* ugp = ugb + (size_t)(t + 3) * Hdim;
            #pragma unroll
            for (int c = 0; c < 2; c++) {
                e4[st][c] = *(const float4*)(ed  + c * 128);
                g4[st][c] = *(const float4*)(ugp + c * 128);
            }
            pv[st][0] = pas[(size_t)(t + 3) * Ndim];
            pv[st][1] = pas[(size_t)(t + 3) * Ndim + 1];
        }

        float cacc[8];
        #pragma unroll
        for (int j = 0; j < 8; j++) {
            float den0  = fmaf(ew[j], En0, 1.0f);
            float beta0 = __fdividef(ab, den0);            // a * sigmoid
            u[0][j] = fmaf(beta0, ugv[j] - u[0][j], u[0][j]);
            float den1  = fmaf(ew[j], En1, 1.0f);
            float beta1 = __fdividef(ab, den1);
            u[1][j] = fmaf(beta1, ugv[j] - u[1][j], u[1][j]);
            cacc[j] = fmaf(u[1][j], p1, u[0][j] * p0);
        }
        float* dst = &sacc[sb][wid * 256 + h0];
        *(float4*)(dst)       = make_float4(cacc[0], cacc[1], cacc[2], cacc[3]);
        *(float4*)(dst + 128) = make_float4(cacc[4], cacc[5], cacc[6], cacc[7]);

        __syncthreads();
        {
            const float* buf = sacc[sb];
            float r0 = 0.f, r1 = 0.f;
            #pragma unroll
            for (int w = 0; w < 4; w++) {
                r0 += buf[w * 256 + tid];
                r1 += buf[w * 256 + 128 + tid];
            }
            atomicAdd(&outb[(size_t)t * Hdim + tid], r0);
            atomicAdd(&outb[(size_t)t * Hdim + 128 + tid], r1);
        }
        // next iteration writes the other buffer; its barrier fences reuse.
    }
}

// ---------------------------------------------------------------------------
extern "C" void kernel_launch(void* const* d_in, const int* in_sizes, int n_in,
                              void* d_out, int out_size)
{
    const float* hidden   = (const float*)d_in[0];
    const float* SE       = (const float*)d_in[1];
    const float* rel_tab  = (const float*)d_in[2];
    const float* sq_w     = (const float*)d_in[3];
    const float* sq_b     = (const float*)d_in[4];
    const float* ae_w     = (const float*)d_in[5];
    const float* ae_b     = (const float*)d_in[6];
    const float* wq_w     = (const float*)d_in[7];
    const float* wq_b     = (const float*)d_in[8];
    const float* wk_w     = (const float*)d_in[9];
    const float* wk_b     = (const float*)d_in[10];
    const float* wd_w     = (const float*)d_in[11];
    const float* wd_b     = (const float*)d_in[12];
    const float* wu_w     = (const float*)d_in[13];
    const float* wu_b     = (const float*)d_in[14];
    const float* wg_w     = (const float*)d_in[15];
    const float* wg_b     = (const float*)d_in[16];
    const int*   heads    = (const int*)d_in[17];
    const int*   tails    = (const int*)d_in[18];
    const int*   tri_mask = (const int*)d_in[19];
    const int*   rel_idx  = (const int*)d_in[20];
    float* out = (float*)d_out;

    const float* h_last = hidden + (size_t)(Ldim - 1) * Bdim * Tdim * Hdim;

    // Dynamic smem for prep_kernel exceeds the 48KB static limit.
    // Attribute set is idempotent and capture-safe (host-side, no allocation).
    cudaFuncSetAttribute(prep_kernel,
                         cudaFuncAttributeMaxDynamicSharedMemorySize,
                         PREP_SMEM_BYTES);

    cudaMemsetAsync(out, 0, (size_t)out_size * sizeof(float), 0);

    prep_kernel<<<1025, 256, PREP_SMEM_BYTES>>>(
        SE, heads, tails, sq_w, sq_b, tri_mask,
        h_last, wq_w, wq_b, wd_w, wd_b, wg_w, wg_b,
        rel_tab, rel_idx, wk_w, wk_b, ae_w, ae_b);
    score_kernel<<<(Bdim * Tdim) / 8, 256>>>(tri_mask);
    scan_kernel<<<dim3(Ndim / 8, Bdim), 128>>>(wu_w, wu_b, out);
}

// round 16
// speedup vs baseline: 1.3047x; 1.3047x over previous
#include <cuda_runtime.h>
#include <cuda_bf16.h>
#include <cstdint>

// Problem dims
#define Ldim 2
#define Bdim 8
#define Tdim 256
#define Ndim 512
#define Kdim 16
#define Mdim 10000
#define Hdim 256
#define Rdim 500

// Scratch (device globals -- no allocation allowed)
__device__ float g_u0[Bdim * Ndim * Hdim];       // 4 MB
__device__ float g_q[Bdim * Tdim * Hdim];        // 2 MB
__device__ float g_k[Bdim * Ndim * Hdim];        // 4 MB
__device__ float g_ewd[Bdim * Tdim * Hdim];      // 2 MB : exp(-(h@wd.T+bd))
__device__ float g_ug[Bdim * Tdim * Hdim];       // 2 MB
__device__ float g_pasi[Bdim * Tdim * Ndim];     // 4 MB
__device__ float g_a[Bdim];

__device__ __forceinline__ float warp_sum(float v) {
    #pragma unroll
    for (int o = 16; o > 0; o >>= 1) v += __shfl_xor_sync(0xffffffffu, v, o);
    return v;
}
__device__ __forceinline__ float warp_max(float v) {
    #pragma unroll
    for (int o = 16; o > 0; o >>= 1) v = fmaxf(v, __shfl_xor_sync(0xffffffffu, v, o));
    return v;
}

#define WT_PITCH 258   // even pitch: float2 reads 8B-aligned & conflict-free

#define PREP_XS_FLOATS   (16 * 512)
#define PREP_WT_FLOATS   (32 * WT_PITCH)
#define PREP_SMEM_BYTES  ((PREP_XS_FLOATS + PREP_WT_FLOATS) * 4 + 512 * 4)

// Cooperatively load a 32(j) x 256(o) tile of a row-major weight W[o][ld]
// into wt[jj*WT_PITCH + o], fully coalesced from global.
__device__ __forceinline__ void load_wtile(
    float* wt, const float* __restrict__ W, int ld, int j0, int tid)
{
    #pragma unroll
    for (int i = 0; i < 8; i++) {
        int lin = i * 256 + tid;          // indexes (o, j4)
        int o   = lin >> 3;
        int j4  = lin & 7;
        float4 w = *(const float4*)(W + (size_t)o * ld + j0 + j4 * 4);
        wt[(j4 * 4 + 0) * WT_PITCH + o] = w.x;
        wt[(j4 * 4 + 1) * WT_PITCH + o] = w.y;
        wt[(j4 * 4 + 2) * WT_PITCH + o] = w.z;
        wt[(j4 * 4 + 3) * WT_PITCH + o] = w.w;
    }
}

// ---------------------------------------------------------------------------
// prep_kernel (round-14 winner, reverted): fused u0 + qdg + k + aerfa with
// SMEM-tiled weights and TMxTN=(8|4)x2 register tiling.
//   blocks [0,256)   : u0 rows (16 each; halves of 128 thr take 8 rows, TN=2)
//   blocks [256,512) : qdg rows (8 each; halves take 4 rows, 3 matrices)
//   blocks [512,768) : k rows (16 each)
//   block  768       : aerfa
// ---------------------------------------------------------------------------
__global__ __launch_bounds__(256) void prep_kernel(
    const float* __restrict__ SE,          // (B,M,H)
    const int*   __restrict__ heads,       // (B,N,K)
    const int*   __restrict__ tails,       // (B,N,K)
    const float* __restrict__ squeeze_w,   // (H,2H)
    const float* __restrict__ squeeze_b,   // (H)
    const int*   __restrict__ tri_mask,    // (B,N)
    const float* __restrict__ hlast,       // (B*T, H)
    const float* __restrict__ wq, const float* __restrict__ bq,
    const float* __restrict__ wd, const float* __restrict__ bd,
    const float* __restrict__ wg, const float* __restrict__ bg,
    const float* __restrict__ rel_table,   // (R,H)
    const int*   __restrict__ ridx_g,      // (B,N)
    const float* __restrict__ wk, const float* __restrict__ bk,
    const float* __restrict__ aw, const float* __restrict__ abias)
{
    extern __shared__ float dyn_smem[];
    float* xs_f   = dyn_smem;                          // 16*512 floats
    float* wt     = dyn_smem + PREP_XS_FLOATS;         // 32*WT_PITCH floats
    int*   smem_i = (int*)(dyn_smem + PREP_XS_FLOATS + PREP_WT_FLOATS);

    const int tid  = threadIdx.x;
    const int blk  = blockIdx.x;
    const int half = tid >> 7;             // 0 or 1 (row-half)
    const int o0   = (tid & 127) * 2;      // this thread's 2 output cols

    if (blk < 256) {
        // ---------------- u0 path: 16 (b,n) rows, K=512 ----------------
        int (*sidx)[32] = (int(*)[32])smem_i;
        const int row0 = blk * 16;
        const int b    = row0 / Ndim;

        for (int i = tid; i < 16 * 32; i += 256) {
            int r = i >> 5, j = i & 31;
            int gr = row0 + r;
            sidx[r][j] = (j < 16) ? heads[gr * Kdim + j] : tails[gr * Kdim + (j - 16)];
        }
        __syncthreads();

        const float* SEb = SE + (size_t)b * Mdim * Hdim;
        for (int r = 0; r < 16; r++) {
            float he = 0.f, te = 0.f;
            #pragma unroll
            for (int k = 0; k < 16; k++) {
                he += SEb[(size_t)sidx[r][k] * Hdim + tid];
                te += SEb[(size_t)sidx[r][16 + k] * Hdim + tid];
            }
            xs_f[r * 512 + tid]       = he;
            xs_f[r * 512 + 256 + tid] = te;
        }
        __syncthreads();

        const int rbase = half * 8;
        float acc[8][2];
        #pragma unroll
        for (int r = 0; r < 8; r++) { acc[r][0] = 0.f; acc[r][1] = 0.f; }

        for (int j0 = 0; j0 < 512; j0 += 32) {
            load_wtile(wt, squeeze_w, 512, j0, tid);
            __syncthreads();
            #pragma unroll
            for (int g = 0; g < 8; g++) {
                float2 wv0 = *(const float2*)&wt[(g*4+0) * WT_PITCH + o0];
                float2 wv1 = *(const float2*)&wt[(g*4+1) * WT_PITCH + o0];
                float2 wv2 = *(const float2*)&wt[(g*4+2) * WT_PITCH + o0];
                float2 wv3 = *(const float2*)&wt[(g*4+3) * WT_PITCH + o0];
                #pragma unroll
                for (int r = 0; r < 8; r++) {
                    float4 xv = *(const float4*)&xs_f[(rbase + r) * 512 + j0 + g*4];
                    acc[r][0] = fmaf(xv.x, wv0.x, acc[r][0]);
                    acc[r][1] = fmaf(xv.x, wv0.y, acc[r][1]);
                    acc[r][0] = fmaf(xv.y, wv1.x, acc[r][0]);
                    acc[r][1] = fmaf(xv.y, wv1.y, acc[r][1]);
                    acc[r][0] = fmaf(xv.z, wv2.x, acc[r][0]);
                    acc[r][1] = fmaf(xv.z, wv2.y, acc[r][1]);
                    acc[r][0] = fmaf(xv.w, wv3.x, acc[r][0]);
                    acc[r][1] = fmaf(xv.w, wv3.y, acc[r][1]);
                }
            }
            __syncthreads();
        }
        float b0 = squeeze_b[o0], b1 = squeeze_b[o0 + 1];
        for (int r = 0; r < 8; r++) {
            int gr = row0 + rbase + r;
            int ok = (tri_mask[gr] == 1);
            float2 v = make_float2(ok ? acc[r][0] + b0 : 0.f,
                                   ok ? acc[r][1] + b1 : 0.f);
            *(float2*)&g_u0[(size_t)gr * Hdim + o0] = v;
        }
    } else if (blk < 512) {
        // ---------------- qdg path: 8 rows, 3 weights, K=256 ----------------
        const int row0 = (blk - 256) * 8;
        for (int r = 0; r < 8; r++)
            xs_f[r * 256 + tid] = hlast[(size_t)(row0 + r) * Hdim + tid];
        __syncthreads();

        const int rbase = half * 4;
        float accq[4][2], accd[4][2], accg[4][2];
        #pragma unroll
        for (int r = 0; r < 4; r++) {
            accq[r][0]=accq[r][1]=accd[r][0]=accd[r][1]=accg[r][0]=accg[r][1]=0.f;
        }

        const float* Ws[3] = {wq, wd, wg};
        #pragma unroll
        for (int wsel = 0; wsel < 3; wsel++) {
            const float* W = Ws[wsel];
            float acc[4][2];
            #pragma unroll
            for (int r = 0; r < 4; r++) { acc[r][0] = 0.f; acc[r][1] = 0.f; }
            for (int j0 = 0; j0 < 256; j0 += 32) {
                load_wtile(wt, W, 256, j0, tid);
                __syncthreads();
                #pragma unroll
                for (int g = 0; g < 8; g++) {
                    float2 wv0 = *(const float2*)&wt[(g*4+0) * WT_PITCH + o0];
                    float2 wv1 = *(const float2*)&wt[(g*4+1) * WT_PITCH + o0];
                    float2 wv2 = *(const float2*)&wt[(g*4+2) * WT_PITCH + o0];
                    float2 wv3 = *(const float2*)&wt[(g*4+3) * WT_PITCH + o0];
                    #pragma unroll
                    for (int r = 0; r < 4; r++) {
                        float4 xv = *(const float4*)&xs_f[(rbase + r) * 256 + j0 + g*4];
                        acc[r][0] = fmaf(xv.x, wv0.x, acc[r][0]);
                        acc[r][1] = fmaf(xv.x, wv0.y, acc[r][1]);
                        acc[r][0] = fmaf(xv.y, wv1.x, acc[r][0]);
                        acc[r][1] = fmaf(xv.y, wv1.y, acc[r][1]);
                        acc[r][0] = fmaf(xv.z, wv2.x, acc[r][0]);
                        acc[r][1] = fmaf(xv.z, wv2.y, acc[r][1]);
                        acc[r][0] = fmaf(xv.w, wv3.x, acc[r][0]);
                        acc[r][1] = fmaf(xv.w, wv3.y, acc[r][1]);
                    }
                }
                __syncthreads();
            }
            #pragma unroll
            for (int r = 0; r < 4; r++) {
                if (wsel == 0)      { accq[r][0] = acc[r][0]; accq[r][1] = acc[r][1]; }
                else if (wsel == 1) { accd[r][0] = acc[r][0]; accd[r][1] = acc[r][1]; }
                else                { accg[r][0] = acc[r][0]; accg[r][1] = acc[r][1]; }
            }
        }
        float bq0 = bq[o0], bq1 = bq[o0+1];
        float bd0 = bd[o0], bd1 = bd[o0+1];
        float bg0 = bg[o0], bg1 = bg[o0+1];
        for (int r = 0; r < 4; r++) {
            size_t o = (size_t)(row0 + rbase + r) * Hdim + o0;
            *(float2*)&g_q[o]   = make_float2((accq[r][0] + bq0) * 0.0625f,
                                              (accq[r][1] + bq1) * 0.0625f);
            *(float2*)&g_ewd[o] = make_float2(__expf(-(accd[r][0] + bd0)),
                                              __expf(-(accd[r][1] + bd1)));
            *(float2*)&g_ug[o]  = make_float2(accg[r][0] + bg0,
                                              accg[r][1] + bg1);
        }
    } else if (blk < 768) {
        // ---------------- k path: 16 rows, K=256 ----------------
        int* ridx = smem_i;
        const int row0 = (blk - 512) * 16;
        if (tid < 16) ridx[tid] = ridx_g[row0 + tid];
        __syncthreads();
        for (int i = tid; i < 16 * 256; i += 256) {
            int r = i >> 8, j = i & 255;
            xs_f[r * 256 + j] = rel_table[(size_t)ridx[r] * Hdim + j];
        }
        __syncthreads();

        const int rbase = half * 8;
        float acc[8][2];
        #pragma unroll
        for (int r = 0; r < 8; r++) { acc[r][0] = 0.f; acc[r][1] = 0.f; }

        for (int j0 = 0; j0 < 256; j0 += 32) {
            load_wtile(wt, wk, 256, j0, tid);
            __syncthreads();
            #pragma unroll
            for (int g = 0; g < 8; g++) {
                float2 wv0 = *(const float2*)&wt[(g*4+0) * WT_PITCH + o0];
                float2 wv1 = *(const float2*)&wt[(g*4+1) * WT_PITCH + o0];
                float2 wv2 = *(const float2*)&wt[(g*4+2) * WT_PITCH + o0];
                float2 wv3 = *(const float2*)&wt[(g*4+3) * WT_PITCH + o0];
                #pragma unroll
                for (int r = 0; r < 8; r++) {
                    float4 xv = *(const float4*)&xs_f[(rbase + r) * 256 + j0 + g*4];
                    acc[r][0] = fmaf(xv.x, wv0.x, acc[r][0]);
                    acc[r][1] = fmaf(xv.x, wv0.y, acc[r][1]);
                    acc[r][0] = fmaf(xv.y, wv1.x, acc[r][0]);
                    acc[r][1] = fmaf(xv.y, wv1.y, acc[r][1]);
                    acc[r][0] = fmaf(xv.z, wv2.x, acc[r][0]);
                    acc[r][1] = fmaf(xv.z, wv2.y, acc[r][1]);
                    acc[r][0] = fmaf(xv.w, wv3.x, acc[r][0]);
                    acc[r][1] = fmaf(xv.w, wv3.y, acc[r][1]);
                }
            }
            __syncthreads();
        }
        float bk0 = bk[o0], bk1 = bk[o0 + 1];
        for (int r = 0; r < 8; r++) {
            size_t o = (size_t)(row0 + rbase + r) * Hdim + o0;
            *(float2*)&g_k[o] = make_float2(acc[r][0] + bk0, acc[r][1] + bk1);
        }
    } else {
        // ---------------- aerfa: warp b handles batch b ----------------
        const int b = tid >> 5, lane = tid & 31;
        const float* x = hlast + ((size_t)b * Tdim + (Tdim - 1)) * Hdim;
        float s = 0.f;
        #pragma unroll
        for (int j = lane; j < Hdim; j += 32) s += x[j] * aw[j];
        s = warp_sum(s);
        if (lane == 0) g_a[b] = __fdividef(1.0f, 1.0f + __expf(-(s + abias[0])));
    }
}

// ---------------------------------------------------------------------------
// Kernel 3: scores = q.k^T (masked) then softmax over n -> pasi
// ---------------------------------------------------------------------------
__global__ __launch_bounds__(256) void score_kernel(const int* __restrict__ tri_mask)
{
    __shared__ float qs[8][256];
    __shared__ float sc[8][512];
    const int tid  = threadIdx.x;
    const int row0 = blockIdx.x * 8;       // flattened b*T + t
    const int b    = row0 / Tdim;

    for (int r = 0; r < 8; r++) qs[r][tid] = g_q[(size_t)(row0 + r) * Hdim + tid];
    __syncthreads();

    float a0[8], a1[8];
    #pragma unroll
    for (int r = 0; r < 8; r++) { a0[r] = 0.f; a1[r] = 0.f; }

    const float* kb = g_k + (size_t)b * Ndim * Hdim;
    const float4* K0 = (const float4*)(kb + (size_t)tid * Hdim);
    const float4* K1 = (const float4*)(kb + (size_t)(tid + 256) * Hdim);
    for (int j4 = 0; j4 < 64; j4++) {
        float4 k0 = K0[j4], k1 = K1[j4];
        #pragma unroll
        for (int r = 0; r < 8; r++) {
            float4 q = *(const float4*)&qs[r][j4 * 4];
            a0[r] += q.x * k0.x + q.y * k0.y + q.z * k0.z + q.w * k0.w;
            a1[r] += q.x * k1.x + q.y * k1.y + q.z * k1.z + q.w * k1.w;
        }
    }
    int m0 = tri_mask[b * Ndim + tid];
    int m1 = tri_mask[b * Ndim + tid + 256];
    for (int r = 0; r < 8; r++) {
        sc[r][tid]       = (m0 == 1) ? a0[r] : -1.0e9f;
        sc[r][tid + 256] = (m1 == 1) ? a1[r] : -1.0e9f;
    }
    __syncthreads();

    const int wid = tid >> 5, lane = tid & 31;
    float* row = sc[wid];
    float mx = -3.4e38f;
    #pragma unroll
    for (int i = lane; i < 512; i += 32) mx = fmaxf(mx, row[i]);
    mx = warp_max(mx);
    float sum = 0.f;
    #pragma unroll
    for (int i = lane; i < 512; i += 32) {
        float e = __expf(row[i] - mx);
        row[i] = e;
        sum += e;
    }
    sum = warp_sum(sum);
    float inv = __fdividef(1.0f, sum);
    float* pout = g_pasi + (size_t)(row0 + wid) * Ndim;
    #pragma unroll
    for (int i = lane; i < 512; i += 32) pout[i] = row[i] * inv;
}

// ---------------------------------------------------------------------------
// Kernel 4: sequential scan, npw=2 + DEPTH-2 PREFETCH + float4 h-mapping
// (round-14 winner, reverted).
// grid: (N/8, B) = 512 blocks x 128 thr (4 warps). Warp owns 2 n; thread owns
// h = c*128 + 4*lane + {0..3}, c=0,1 (LDG.128, fully coalesced).
// ---------------------------------------------------------------------------
__global__ __launch_bounds__(128) void scan_kernel(
    const float* __restrict__ wu_w,        // (1,H)
    const float* __restrict__ wu_b,        // (1)
    float* __restrict__ out)               // (B,T,H)
{
    __shared__ float sacc[2][1024];        // 4 warps x 256 h, x2 buf
    const int b    = blockIdx.y;
    const int wid  = threadIdx.x >> 5;     // 0..3
    const int lane = threadIdx.x & 31;
    const int tid  = threadIdx.x;          // 0..127
    const int n0   = blockIdx.x * 8 + wid * 2;    // this warp's 2 n
    const int h0   = lane * 4;                    // offset within 128-chunk

    float u[2][8], wv[8];
    #pragma unroll
    for (int c = 0; c < 2; c++) {
        float4 ww = *(const float4*)(wu_w + c * 128 + h0);
        wv[c*4+0]=ww.x; wv[c*4+1]=ww.y; wv[c*4+2]=ww.z; wv[c*4+3]=ww.w;
    }
    #pragma unroll
    for (int m = 0; m < 2; m++) {
        const float* ubase = g_u0 + ((size_t)b * Ndim + n0 + m) * Hdim;
        #pragma unroll
        for (int c = 0; c < 2; c++) {
            float4 uu = *(const float4*)(ubase + c * 128 + h0);
            u[m][c*4+0]=uu.x; u[m][c*4+1]=uu.y; u[m][c*4+2]=uu.z; u[m][c*4+3]=uu.w;
        }
    }
    const float wub = wu_b[0];
    const float ab  = g_a[b];
    const float* pas = g_pasi + (size_t)b * Tdim * Ndim + n0;
    const float* edb = g_ewd + (size_t)b * Tdim * Hdim + h0;
    const float* ugb = g_ug  + (size_t)b * Tdim * Hdim + h0;
    float* outb = out + (size_t)b * Tdim * Hdim;

    // 2-stage pipeline: stage[s] holds data for t with (t & 1) == s
    float4 e4[2][2], g4[2][2];   // [stage][chunk]
    float  pv[2][2];             // [stage][m]
    #pragma unroll
    for (int s = 0; s < 2; s++) {
        const float* ed  = edb + (size_t)s * Hdim;
        const float* ugp = ugb + (size_t)s * Hdim;
        #pragma unroll
        for (int c = 0; c < 2; c++) {
            e4[s][c] = *(const float4*)(ed  + c * 128);
            g4[s][c] = *(const float4*)(ugp + c * 128);
        }
        pv[s][0] = pas[(size_t)s * Ndim];
        pv[s][1] = pas[(size_t)s * Ndim + 1];
    }

    #pragma unroll 2
    for (int t = 0; t < Tdim; t++) {
        const int st = t & 1;

        // copy stage to locals (frees the stage for the t+2 prefetch below)
        float ew[8]  = {e4[st][0].x, e4[st][0].y, e4[st][0].z, e4[st][0].w,
                        e4[st][1].x, e4[st][1].y, e4[st][1].z, e4[st][1].w};
        float ugv[8] = {g4[st][0].x, g4[st][0].y, g4[st][0].z, g4[st][0].w,
                        g4[st][1].x, g4[st][1].y, g4[st][1].z, g4[st][1].w};
        float p0 = pv[st][0], p1 = pv[st][1];

        // wu[m] = u[m] . wu_w + wu_b  (PRE-update u)
        float s0 = 0.f, s1 = 0.f;
        #pragma unroll
        for (int j = 0; j < 8; j++) {
            s0 = fmaf(u[0][j], wv[j], s0);
            s1 = fmaf(u[1][j], wv[j], s1);
        }
        #pragma unroll
        for (int o = 16; o > 0; o >>= 1) {
            s0 += __shfl_xor_sync(0xffffffffu, s0, o);
            s1 += __shfl_xor_sync(0xffffffffu, s1, o);
        }
        float En0 = __expf(-(s0 + wub));
        float En1 = __expf(-(s1 + wub));

        // prefetch t+2 into stage st (consumed two iterations from now)
        if (t + 2 < Tdim) {
            const float* ed  = edb + (size_t)(t + 2) * Hdim;
            const float* ugp = ugb + (size_t)(t + 2) * Hdim;
            #pragma unroll
            for (int c = 0; c < 2; c++) {
                e4[st][c] = *(const float4*)(ed  + c * 128);
                g4[st][c] = *(const float4*)(ugp + c * 128);
            }
            pv[st][0] = pas[(size_t)(t + 2) * Ndim];
            pv[st][1] = pas[(size_t)(t + 2) * Ndim + 1];
        }

        float cacc[8];
        #pragma unroll
        for (int j = 0; j < 8; j++) {
            float den0  = fmaf(ew[j], En0, 1.0f);
            float beta0 = __fdividef(ab, den0);            // a * sigmoid
            u[0][j] = fmaf(beta0, ugv[j] - u[0][j], u[0][j]);
            float den1  = fmaf(ew[j], En1, 1.0f);
            float beta1 = __fdividef(ab, den1);
            u[1][j] = fmaf(beta1, ugv[j] - u[1][j], u[1][j]);
            cacc[j] = fmaf(u[1][j], p1, u[0][j] * p0);
        }
        float* dst = &sacc[st][wid * 256 + h0];
        *(float4*)(dst)       = make_float4(cacc[0], cacc[1], cacc[2], cacc[3]);
        *(float4*)(dst + 128) = make_float4(cacc[4], cacc[5], cacc[6], cacc[7]);

        __syncthreads();
        {
            const float* buf = sacc[st];
            float r0 = 0.f, r1 = 0.f;
            #pragma unroll
            for (int w = 0; w < 4; w++) {
                r0 += buf[w * 256 + tid];
                r1 += buf[w * 256 + 128 + tid];
            }
            atomicAdd(&outb[(size_t)t * Hdim + tid], r0);
            atomicAdd(&outb[(size_t)t * Hdim + 128 + tid], r1);
        }
        // next iteration writes the other buffer; its barrier fences reuse.
    }
}

// ---------------------------------------------------------------------------
extern "C" void kernel_launch(void* const* d_in, const int* in_sizes, int n_in,
                              void* d_out, int out_size)
{
    const float* hidden   = (const float*)d_in[0];
    const float* SE       = (const float*)d_in[1];
    const float* rel_tab  = (const float*)d_in[2];
    const float* sq_w     = (const float*)d_in[3];
    const float* sq_b     = (const float*)d_in[4];
    const float* ae_w     = (const float*)d_in[5];
    const float* ae_b     = (const float*)d_in[6];
    const float* wq_w     = (const float*)d_in[7];
    const float* wq_b     = (const float*)d_in[8];
    const float* wk_w     = (const float*)d_in[9];
    const float* wk_b     = (const float*)d_in[10];
    const float* wd_w     = (const float*)d_in[11];
    const float* wd_b     = (const float*)d_in[12];
    const float* wu_w     = (const float*)d_in[13];
    const float* wu_b     = (const float*)d_in[14];
    const float* wg_w     = (const float*)d_in[15];
    const float* wg_b     = (const float*)d_in[16];
    const int*   heads    = (const int*)d_in[17];
    const int*   tails    = (const int*)d_in[18];
    const int*   tri_mask = (const int*)d_in[19];
    const int*   rel_idx  = (const int*)d_in[20];
    float* out = (float*)d_out;

    const float* h_last = hidden + (size_t)(Ldim - 1) * Bdim * Tdim * Hdim;

    // Dynamic smem for prep_kernel exceeds the 48KB static limit.
    // Attribute set is idempotent and capture-safe (host-side, no allocation).
    cudaFuncSetAttribute(prep_kernel,
                         cudaFuncAttributeMaxDynamicSharedMemorySize,
                         PREP_SMEM_BYTES);

    cudaMemsetAsync(out, 0, (size_t)out_size * sizeof(float), 0);

    prep_kernel<<<769, 256, PREP_SMEM_BYTES>>>(
        SE, heads, tails, sq_w, sq_b, tri_mask,
        h_last, wq_w, wq_b, wd_w, wd_b, wg_w, wg_b,
        rel_tab, rel_idx, wk_w, wk_b, ae_w, ae_b);
    score_kernel<<<(Bdim * Tdim) / 8, 256>>>(tri_mask);
    scan_kernel<<<dim3(Ndim / 8, Bdim), 128>>>(wu_w, wu_b, out);
}